// round 12
// baseline (speedup 1.0000x reference)
#include <cuda_runtime.h>
#include <cuda_fp16.h>
#include <math_constants.h>
#include <cstdint>

#define B_  4
#define N_  4096
#define C_  256
#define NT_ 64   // key tiles of 64
#define NP_ 320  // packed projection cols: 32 f + 32 g(pre-scaled by log2e) + 256 h

// ---------------------------------------------------------------------------
// Scratch (__device__ globals; allocation-free rule)
// ---------------------------------------------------------------------------
__device__ uint4 g_xs[B_ * N_ * 64];          // x split fp16 [BN][256hi|256lo]
__device__ uint4 g_wt[NP_ * 64];              // W^T split fp16 [320][256hi|256lo]
__device__ float g_pb[NP_];                   // packed bias
__device__ uint4 g_fs[B_ * N_ * 8];           // F split fp16 [B,N,(32hi|32lo)]
__device__ uint4 g_gs[B_ * N_ * 8];           // G split fp16 [B,N,(32hi|32lo)]
__device__ uint4 g_ht[B_ * C_ * N_ / 8];      // H^T fp16 [B,C,N]

// ---------------------------------------------------------------------------
// Helpers
// ---------------------------------------------------------------------------
__device__ __forceinline__ uint32_t smem_u32(const void* p) {
    uint32_t a;
    asm("{ .reg .u64 t; cvta.to.shared.u64 t, %1; cvt.u32.u64 %0, t; }" : "=r"(a) : "l"(p));
    return a;
}
__device__ __forceinline__ void ldsm4(uint32_t* r, uint32_t addr) {
    asm volatile("ldmatrix.sync.aligned.m8n8.x4.shared.b16 {%0,%1,%2,%3}, [%4];"
        : "=r"(r[0]), "=r"(r[1]), "=r"(r[2]), "=r"(r[3]) : "r"(addr));
}
__device__ __forceinline__ void mma_f16(float* d, const uint32_t* a, uint32_t b0, uint32_t b1) {
    asm volatile("mma.sync.aligned.m16n8k16.row.col.f32.f16.f16.f32 "
        "{%0,%1,%2,%3}, {%4,%5,%6,%7}, {%8,%9}, {%0,%1,%2,%3};"
        : "+f"(d[0]), "+f"(d[1]), "+f"(d[2]), "+f"(d[3])
        : "r"(a[0]), "r"(a[1]), "r"(a[2]), "r"(a[3]), "r"(b0), "r"(b1));
}
__device__ __forceinline__ void cp16(uint32_t dst, const void* src) {
    asm volatile("cp.async.cg.shared.global [%0], [%1], 16;" :: "r"(dst), "l"(src) : "memory");
}
__device__ __forceinline__ float ex2(float x) {
    float y; asm("ex2.approx.f32 %0, %1;" : "=f"(y) : "f"(x)); return y;
}
#define CP_COMMIT()  asm volatile("cp.async.commit_group;" ::: "memory")
#define CP_WAIT(n)   asm volatile("cp.async.wait_group %0;" :: "n"(n) : "memory")

// ---------------------------------------------------------------------------
// prep_x: x fp32 [BN,256] -> xs fp16 [BN][256hi|256lo]
// ---------------------------------------------------------------------------
__global__ __launch_bounds__(256) void prep_x(const float* __restrict__ x, uint4* __restrict__ xs)
{
    int id = blockIdx.x * 256 + threadIdx.x;
    int r = id >> 5, c = id & 31;
    const float4* src = (const float4*)(x + (long)r * 256 + c * 8);
    float4 v0 = src[0], v1 = src[1];
    float vv[8] = {v0.x, v0.y, v0.z, v0.w, v1.x, v1.y, v1.z, v1.w};
    __half hv[8], lv[8];
#pragma unroll
    for (int i = 0; i < 8; i++) {
        hv[i] = __float2half_rn(vv[i]);
        lv[i] = __float2half_rn(vv[i] - __half2float(hv[i]));
    }
    xs[(long)r * 64 + c]      = *(uint4*)hv;
    xs[(long)r * 64 + 32 + c] = *(uint4*)lv;
}

// ---------------------------------------------------------------------------
// prep_w: pack [Wf|Wg*log2e|Wh]^T fp16 hi/lo + bias.
// ---------------------------------------------------------------------------
__global__ __launch_bounds__(256) void prep_w(
    const float* __restrict__ Wf, const float* __restrict__ Wg, const float* __restrict__ Wh,
    const float* __restrict__ bf, const float* __restrict__ bg, const float* __restrict__ bh,
    __half* __restrict__ wt, float* __restrict__ pb)
{
    const float L2E = 1.4426950408889634f;
    int n = blockIdx.x, k = threadIdx.x;
    float w = (n < 32) ? Wf[k * 32 + n]
            : (n < 64) ? Wg[k * 32 + (n - 32)] * L2E
                       : Wh[k * 256 + (n - 64)];
    __half hv = __float2half_rn(w);
    __half lv = __float2half_rn(w - __half2float(hv));
    wt[(long)n * 512 + k] = hv;
    wt[(long)n * 512 + 256 + k] = lv;
    if (k == 0)
        pb[n] = (n < 32) ? bf[n] : (n < 64) ? bg[n - 32] * L2E : bh[n - 64];
}

// ---------------------------------------------------------------------------
// Fused projection GEMM + transposed h epilogue (unchanged from round 9).
// ---------------------------------------------------------------------------
#define PG_STAGE 49152
#define PG_SMEM  (2 * PG_STAGE + 256)

__global__ __launch_bounds__(256) void proj_mma(
    const uint4* __restrict__ xs, const uint4* __restrict__ wt,
    const float* __restrict__ pb,
    __half* __restrict__ fsh, __half* __restrict__ gsh, __half* __restrict__ ht)
{
    extern __shared__ char smem[];
    const uint32_t sb = smem_u32(smem);
    float* sbias = (float*)(smem + 2 * PG_STAGE);
    const int tid = threadIdx.x, lane = tid & 31, wid = tid >> 5;
    const int wm = wid & 3, wn = wid >> 2;
    const int n0 = blockIdx.x * 64, m0 = blockIdx.y * 128;

    const int la_row = (((lane >> 3) & 1) << 3) | (lane & 7);
    const int la_sel = lane >> 4;
    const int lb_row = ((lane >> 4) << 3) | (lane & 7);
    const int lb_sel = (lane >> 3) & 1;

    if (tid < 64) sbias[tid] = pb[n0 + tid];

    auto issue_stage = [&](int kt, int st) {
        uint32_t base = sb + st * PG_STAGE;
#pragma unroll
        for (int i = 0; i < 4; i++) {
            int idx = tid + i * 256;
            int r = idx >> 3, c = idx & 7;
            uint32_t sw = ((c ^ (r & 7)) << 4);
            cp16(base + r * 128 + sw,          xs + (long)(m0 + r) * 64 + kt * 8 + c);
            cp16(base + 16384 + r * 128 + sw,  xs + (long)(m0 + r) * 64 + 32 + kt * 8 + c);
        }
#pragma unroll
        for (int i = 0; i < 2; i++) {
            int idx = tid + i * 256;
            int r = idx >> 3, c = idx & 7;
            uint32_t sw = ((c ^ (r & 7)) << 4);
            cp16(base + 32768 + r * 128 + sw,        wt + (long)(n0 + r) * 64 + kt * 8 + c);
            cp16(base + 32768 + 8192 + r * 128 + sw, wt + (long)(n0 + r) * 64 + 32 + kt * 8 + c);
        }
        CP_COMMIT();
    };

    issue_stage(0, 0);

    float d[2][4][4];
#pragma unroll
    for (int mh = 0; mh < 2; mh++)
#pragma unroll
        for (int i = 0; i < 4; i++)
#pragma unroll
            for (int j = 0; j < 4; j++) d[mh][i][j] = 0.f;

#pragma unroll 1
    for (int kt = 0; kt < 4; kt++) {
        if (kt < 3) { issue_stage(kt + 1, (kt + 1) & 1); CP_WAIT(1); }
        else        { CP_WAIT(0); }
        __syncthreads();
        uint32_t buf = sb + (kt & 1) * PG_STAGE;

#pragma unroll
        for (int kc = 0; kc < 4; kc++) {
            uint32_t ah[2][4], al[2][4], bh[2][4], bl[2][4];
#pragma unroll
            for (int mh = 0; mh < 2; mh++) {
                int arow = wm * 32 + mh * 16 + la_row;
                uint32_t sw = (((2 * kc + la_sel) ^ (arow & 7)) << 4);
                ldsm4(ah[mh], buf + arow * 128 + sw);
                ldsm4(al[mh], buf + 16384 + arow * 128 + sw);
            }
#pragma unroll
            for (int n16 = 0; n16 < 2; n16++) {
                int brow = wn * 32 + n16 * 16 + lb_row;
                uint32_t sw = (((2 * kc + lb_sel) ^ (brow & 7)) << 4);
                ldsm4(bh[n16], buf + 32768 + brow * 128 + sw);
                ldsm4(bl[n16], buf + 32768 + 8192 + brow * 128 + sw);
            }
#pragma unroll
            for (int mh = 0; mh < 2; mh++)
#pragma unroll
                for (int n16 = 0; n16 < 2; n16++)
#pragma unroll
                    for (int j = 0; j < 2; j++) {
                        float* dd = d[mh][n16 * 2 + j];
                        mma_f16(dd, ah[mh], bh[n16][2 * j], bh[n16][2 * j + 1]);
                        mma_f16(dd, ah[mh], bl[n16][2 * j], bl[n16][2 * j + 1]);
                        mma_f16(dd, al[mh], bh[n16][2 * j], bh[n16][2 * j + 1]);
                    }
        }
        __syncthreads();
    }

    if (blockIdx.x == 0) {
#pragma unroll
        for (int mh = 0; mh < 2; mh++) {
            const long mrow0 = m0 + wm * 32 + mh * 16 + (lane >> 2);
            const long mrow1 = mrow0 + 8;
#pragma unroll
            for (int n16 = 0; n16 < 2; n16++)
#pragma unroll
                for (int j = 0; j < 2; j++) {
                    const float* dd = d[mh][n16 * 2 + j];
                    int col = wn * 32 + n16 * 16 + j * 8 + (lane & 3) * 2;
                    float b0 = sbias[col], b1 = sbias[col + 1];
                    float v00 = dd[0] + b0, v01 = dd[1] + b1;
                    float v10 = dd[2] + b0, v11 = dd[3] + b1;
                    __half* dst = (col < 32) ? fsh : gsh;
                    int c = col & 31;
                    __half2 h0 = __floats2half2_rn(v00, v01);
                    float2 f0 = __half22float2(h0);
                    __half2 l0 = __floats2half2_rn(v00 - f0.x, v01 - f0.y);
                    *(__half2*)(dst + mrow0 * 64 + c) = h0;
                    *(__half2*)(dst + mrow0 * 64 + 32 + c) = l0;
                    __half2 h1 = __floats2half2_rn(v10, v11);
                    float2 f1 = __half22float2(h1);
                    __half2 l1 = __floats2half2_rn(v10 - f1.x, v11 - f1.y);
                    *(__half2*)(dst + mrow1 * 64 + c) = h1;
                    *(__half2*)(dst + mrow1 * 64 + 32 + c) = l1;
                }
        }
    } else {
        __half* sT = (__half*)smem;            // [64 ch][136 stride]
#pragma unroll
        for (int mh = 0; mh < 2; mh++) {
            const int r0 = wm * 32 + mh * 16 + (lane >> 2);
            const int r1 = r0 + 8;
#pragma unroll
            for (int n16 = 0; n16 < 2; n16++)
#pragma unroll
                for (int j = 0; j < 2; j++) {
                    const float* dd = d[mh][n16 * 2 + j];
                    int col = wn * 32 + n16 * 16 + j * 8 + (lane & 3) * 2;
                    float b0 = sbias[col], b1 = sbias[col + 1];
                    sT[col * 136 + r0]       = __float2half_rn(dd[0] + b0);
                    sT[(col + 1) * 136 + r0] = __float2half_rn(dd[1] + b1);
                    sT[col * 136 + r1]       = __float2half_rn(dd[2] + b0);
                    sT[(col + 1) * 136 + r1] = __float2half_rn(dd[3] + b1);
                }
        }
        __syncthreads();
        const int b = m0 >> 12;
        const int noff = m0 & (N_ - 1);
        const int ch = tid >> 2, q = tid & 3;
        uint4* dst = (uint4*)(ht + ((long)b * C_ + (n0 - 64) + ch) * N_ + noff + q * 32);
        const uint4* srcp = (const uint4*)(sT + ch * 136 + q * 32);
#pragma unroll
        for (int i = 0; i < 4; i++) dst[i] = srcp[i];
    }
}

// ---------------------------------------------------------------------------
// Attention: block = 128 q-rows x batch, 8 warps, 256 threads, 1 CTA/SM.
// MMA1/softmax: 8 row-owner warps (16 q each).  P (fp16) + per-row rescale
// factors exchanged through smem; MMA2 re-tiles warps 2(m=64q) x 4(n=64ch)
// so each Ht B-fragment is read by ONE warp -> smem traffic 368->256 KB/tile.
// Softmax in log2 domain -> raw ex2.  3-stage cp.async ring.
// ---------------------------------------------------------------------------
#define OFF_SG     0                         // G: 16 KB
#define OFF_SP     16384                     // P: 16 KB
#define OFF_SA     32768                     // a[128]: 512 B
#define OFF_SL     33280                     // linv[128]: 512 B
#define OFF_STG    33792
#define STAGE_SZ   (8192 + 32768)            // F + Ht = 40 KB
#define OFF_SF(s)  (OFF_STG + (s) * STAGE_SZ)
#define OFF_SH(s)  (OFF_SF(s) + 8192)
#define SMEM_TOTAL (OFF_STG + 3 * STAGE_SZ)  // 156672 B

__global__ __launch_bounds__(256, 1) void attn_mma(
    const uint4* __restrict__ fsplit, const uint4* __restrict__ gsplit,
    const uint4* __restrict__ ht4,
    const float* __restrict__ x, const float* __restrict__ gamma, float* __restrict__ y)
{
    extern __shared__ char smem[];
    const uint32_t sb = smem_u32(smem);
    const int tid = threadIdx.x, lane = tid & 31, wid = tid >> 5;
    const int b = blockIdx.y, q0 = blockIdx.x * 128;
    const int mw = wid >> 2, wn = wid & 3;           // MMA2 tiling: 2m x 4n

    const int la_row = (((lane >> 3) & 1) << 3) | (lane & 7);
    const int la_sel = lane >> 4;
    const int lb_row = ((lane >> 4) << 3) | (lane & 7);
    const int lb_sel = (lane >> 3) & 1;

    const int hr = tid >> 3, hc = tid & 7;
    const long hbase = (long)b * C_ * (N_ / 8);
    const long fbase = (long)b * N_ * 8;

    float* sa = (float*)(smem + OFF_SA);
    float* sl = (float*)(smem + OFF_SL);

    auto stage_attn = [&](int t) {
        const int sn = t % 3;
#pragma unroll
        for (int i = 0; i < 2; i++) {
            int idx = tid + i * 256;
            int r = idx >> 3, c = idx & 7;
            cp16(sb + OFF_SF(sn) + r * 128 + (((c) ^ (r & 7)) << 4),
                 fsplit + fbase + (long)(t * 64 + r) * 8 + c);
        }
#pragma unroll
        for (int i = 0; i < 8; i++) {
            int r = hr + i * 32;
            cp16(sb + OFF_SH(sn) + r * 128 + (((hc) ^ (r & 7)) << 4),
                 ht4 + hbase + (long)r * (N_ / 8) + t * 8 + hc);
        }
        CP_COMMIT();
    };

    // ---- load G tile [128 rows x 128B], swizzled ----
#pragma unroll
    for (int i = 0; i < 4; i++) {
        int idx = tid + i * 256;
        int r = idx >> 3, c = idx & 7;
        uint4 v = gsplit[(long)(b * N_ + q0 + r) * 8 + c];
        *(uint4*)(smem + OFF_SG + r * 128 + (((c) ^ (r & 7)) << 4)) = v;
    }

    // ---- prologue: issue stages 0 and 1 ----
    stage_attn(0);
    stage_attn(1);

    // ---- hoist G A-fragments (constant over tiles; this warp's 16 rows) ----
    __syncthreads();
    uint32_t gh[2][4], gl[2][4];
    {
        int row = wid * 16 + la_row;
        uint32_t rowoff = sb + OFF_SG + row * 128;
#pragma unroll
        for (int kc = 0; kc < 2; kc++) {
            ldsm4(gh[kc], rowoff + ((((2 * kc) + la_sel) ^ (row & 7)) << 4));
            ldsm4(gl[kc], rowoff + ((((4 + 2 * kc) + la_sel) ^ (row & 7)) << 4));
        }
    }

    // MMA2 accumulators: this warp owns rows [mw*64, +64) x channels [wn*64, +64)
    float o[4][8][4];
#pragma unroll
    for (int i = 0; i < 4; i++)
#pragma unroll
        for (int q = 0; q < 8; q++)
#pragma unroll
            for (int j = 0; j < 4; j++) o[i][q][j] = 0.f;
    float lsum0 = 0.f, lsum1 = 0.f;
    float mrun0 = -CUDART_INF_F, mrun1 = -CUDART_INF_F;

#pragma unroll 1
    for (int t = 0; t < NT_; t++) {
        const int s = t % 3;
        CP_WAIT(1);
        __syncthreads();

        // ---- MMA1(t): S[16x64] (rows 16*wid) in log2 domain, 3-term ----
        float sv[8][4];
#pragma unroll
        for (int i = 0; i < 8; i++)
#pragma unroll
            for (int j = 0; j < 4; j++) sv[i][j] = 0.f;

        {
            const uint32_t sfb = sb + OFF_SF(s);
#pragma unroll
            for (int n16 = 0; n16 < 4; n16++) {
                int row = n16 * 16 + lb_row;
                uint32_t rowoff = sfb + row * 128;
                uint32_t fh0[4], fh1[4], fl0[4], fl1[4];
                ldsm4(fh0, rowoff + (((0 + lb_sel) ^ (row & 7)) << 4));
                ldsm4(fh1, rowoff + (((2 + lb_sel) ^ (row & 7)) << 4));
                ldsm4(fl0, rowoff + (((4 + lb_sel) ^ (row & 7)) << 4));
                ldsm4(fl1, rowoff + (((6 + lb_sel) ^ (row & 7)) << 4));
#pragma unroll
                for (int j = 0; j < 2; j++) {
                    float* sd = sv[n16 * 2 + j];
                    mma_f16(sd, gh[0], fh0[2 * j], fh0[2 * j + 1]);
                    mma_f16(sd, gh[1], fh1[2 * j], fh1[2 * j + 1]);
                    mma_f16(sd, gh[0], fl0[2 * j], fl0[2 * j + 1]);
                    mma_f16(sd, gh[1], fl1[2 * j], fl1[2 * j + 1]);
                    mma_f16(sd, gl[0], fh0[2 * j], fh0[2 * j + 1]);
                    mma_f16(sd, gl[1], fh1[2 * j], fh1[2 * j + 1]);
                }
            }
        }

        // ---- softmax(t): row max + FA2 state + exp2 pack ----
        float mt0 = -CUDART_INF_F, mt1 = -CUDART_INF_F;
#pragma unroll
        for (int i = 0; i < 8; i++) {
            mt0 = fmaxf(mt0, fmaxf(sv[i][0], sv[i][1]));
            mt1 = fmaxf(mt1, fmaxf(sv[i][2], sv[i][3]));
        }
        mt0 = fmaxf(mt0, __shfl_xor_sync(0xFFFFFFFFu, mt0, 1));
        mt0 = fmaxf(mt0, __shfl_xor_sync(0xFFFFFFFFu, mt0, 2));
        mt1 = fmaxf(mt1, __shfl_xor_sync(0xFFFFFFFFu, mt1, 1));
        mt1 = fmaxf(mt1, __shfl_xor_sync(0xFFFFFFFFu, mt1, 2));

        const float mn0 = fmaxf(mrun0, mt0);
        const float mn1 = fmaxf(mrun1, mt1);
        const float a0 = ex2(mrun0 - mn0);   // 0 on first tile
        const float a1 = ex2(mrun1 - mn1);
        mrun0 = mn0; mrun1 = mn1;
        lsum0 *= a0; lsum1 *= a1;

        {
            const int r = lane >> 2, cq = lane & 3;
            const int row0 = wid * 16 + r, row1 = row0 + 8;
#pragma unroll
            for (int kc = 0; kc < 4; kc++) {
#pragma unroll
                for (int j = 0; j < 2; j++) {
                    float* sd = sv[2 * kc + j];
                    float p0 = ex2(sd[0] - mn0);
                    float p1 = ex2(sd[1] - mn0);
                    float p2 = ex2(sd[2] - mn1);
                    float p3 = ex2(sd[3] - mn1);
                    lsum0 += p0 + p1;
                    lsum1 += p2 + p3;
                    __half2 h01 = __floats2half2_rn(p0, p1);
                    __half2 h23 = __floats2half2_rn(p2, p3);
                    int chunk = 2 * kc + j;
                    *(uint32_t*)(smem + OFF_SP + row0 * 128 +
                                 (((chunk) ^ (row0 & 7)) << 4) + cq * 4) = *(uint32_t*)&h01;
                    *(uint32_t*)(smem + OFF_SP + row1 * 128 +
                                 (((chunk) ^ (row1 & 7)) << 4) + cq * 4) = *(uint32_t*)&h23;
                }
            }
            if (cq == 0) {
                sa[wid * 16 + r] = a0;
                sa[wid * 16 + 8 + r] = a1;
            }
        }
        __syncthreads();   // P + a visible to all warps

        // ---- rescale o by per-row a (cross-warp rows) ----
        {
            float ar[8];
#pragma unroll
            for (int i = 0; i < 4; i++) {
                ar[2 * i]     = sa[mw * 64 + i * 16 + (lane >> 2)];
                ar[2 * i + 1] = sa[mw * 64 + i * 16 + 8 + (lane >> 2)];
            }
#pragma unroll
            for (int i = 0; i < 4; i++) {
                float aA = ar[2 * i], aB = ar[2 * i + 1];
                if (aA != 1.f) {
#pragma unroll
                    for (int q = 0; q < 8; q++) { o[i][q][0] *= aA; o[i][q][1] *= aA; }
                }
                if (aB != 1.f) {
#pragma unroll
                    for (int q = 0; q < 8; q++) { o[i][q][2] *= aB; o[i][q][3] *= aB; }
                }
            }
        }

        // ---- MMA2(t): warp tile = rows [mw*64,+64) x ch [wn*64,+64) ----
        {
            const uint32_t shb = sb + OFF_SH(s);
            const uint32_t spb = sb + OFF_SP;
#pragma unroll
            for (int kc = 0; kc < 4; kc++) {
                uint32_t af[4][4];
#pragma unroll
                for (int i = 0; i < 4; i++) {
                    int row = mw * 64 + i * 16 + la_row;
                    ldsm4(af[i], spb + row * 128 + ((((2 * kc) + la_sel) ^ (row & 7)) << 4));
                }
#pragma unroll
                for (int n16 = 0; n16 < 4; n16++) {
                    int row = wn * 64 + n16 * 16 + lb_row;
                    uint32_t bh[4];
                    ldsm4(bh, shb + row * 128 + ((((2 * kc) + lb_sel) ^ (row & 7)) << 4));
#pragma unroll
                    for (int i = 0; i < 4; i++) {
                        mma_f16(o[i][n16 * 2 + 0], af[i], bh[0], bh[1]);
                        mma_f16(o[i][n16 * 2 + 1], af[i], bh[2], bh[3]);
                    }
                }
            }
        }

        // ---- issue stage t+2 (slot (t+2)%3 last read at iter t-1) ----
        if (t + 2 < NT_) stage_attn(t + 2);
        else CP_COMMIT();
    }

    // ---- row-owners publish 1/l ----
    lsum0 += __shfl_xor_sync(0xFFFFFFFFu, lsum0, 1);
    lsum0 += __shfl_xor_sync(0xFFFFFFFFu, lsum0, 2);
    lsum1 += __shfl_xor_sync(0xFFFFFFFFu, lsum1, 1);
    lsum1 += __shfl_xor_sync(0xFFFFFFFFu, lsum1, 2);
    if ((lane & 3) == 0) {
        sl[wid * 16 + (lane >> 2)] = 1.f / lsum0;
        sl[wid * 16 + 8 + (lane >> 2)] = 1.f / lsum1;
    }
    __syncthreads();
    const float gam = gamma[0];

    // ---- epilogue: y = gamma * O/l + x  (rows mw*64.., ch wn*64..) ----
#pragma unroll
    for (int i = 0; i < 4; i++) {
        const int rloc = mw * 64 + i * 16 + (lane >> 2);
        const float li0 = sl[rloc], li1 = sl[rloc + 8];
        const long row0g = ((long)b * N_ + q0 + rloc) * C_;
        const long row1g = row0g + 8 * C_;
#pragma unroll
        for (int n16 = 0; n16 < 4; n16++) {
#pragma unroll
            for (int j = 0; j < 2; j++) {
                const float* od = o[i][n16 * 2 + j];
                int ch = wn * 64 + n16 * 16 + j * 8 + (lane & 3) * 2;
                float2 xv = *(const float2*)(x + row0g + ch);
                float2 yv;
                yv.x = fmaf(gam, od[0] * li0, xv.x);
                yv.y = fmaf(gam, od[1] * li0, xv.y);
                *(float2*)(y + row0g + ch) = yv;
                xv = *(const float2*)(x + row1g + ch);
                yv.x = fmaf(gam, od[2] * li1, xv.x);
                yv.y = fmaf(gam, od[3] * li1, xv.y);
                *(float2*)(y + row1g + ch) = yv;
            }
        }
    }
}

// ---------------------------------------------------------------------------
extern "C" void kernel_launch(void* const* d_in, const int* in_sizes, int n_in,
                              void* d_out, int out_size)
{
    const float* x     = (const float*)d_in[0];
    const float* Wf    = (const float*)d_in[1];
    const float* bf    = (const float*)d_in[2];
    const float* Wg    = (const float*)d_in[3];
    const float* bg    = (const float*)d_in[4];
    const float* Wh    = (const float*)d_in[5];
    const float* bh    = (const float*)d_in[6];
    const float* gamma = (const float*)d_in[7];
    float* y = (float*)d_out;

    void *xs, *wt, *pb, *fs, *gs, *ht;
    cudaGetSymbolAddress(&xs, g_xs);
    cudaGetSymbolAddress(&wt, g_wt);
    cudaGetSymbolAddress(&pb, g_pb);
    cudaGetSymbolAddress(&fs, g_fs);
    cudaGetSymbolAddress(&gs, g_gs);
    cudaGetSymbolAddress(&ht, g_ht);

    const int M = B_ * N_;

    prep_x<<<M * 32 / 256, 256>>>(x, (uint4*)xs);
    prep_w<<<NP_, 256>>>(Wf, Wg, Wh, bf, bg, bh, (__half*)wt, (float*)pb);

    cudaFuncSetAttribute(proj_mma, cudaFuncAttributeMaxDynamicSharedMemorySize, PG_SMEM);
    proj_mma<<<dim3(NP_ / 64, M / 128), 256, PG_SMEM>>>(
        (const uint4*)xs, (const uint4*)wt, (const float*)pb,
        (__half*)fs, (__half*)gs, (__half*)ht);

    cudaFuncSetAttribute(attn_mma, cudaFuncAttributeMaxDynamicSharedMemorySize, SMEM_TOTAL);
    attn_mma<<<dim3(N_ / 128, B_), 256, SMEM_TOTAL>>>(
        (const uint4*)fs, (const uint4*)gs, (const uint4*)ht, x, gamma, y);
}

// round 13
// speedup vs baseline: 1.0684x; 1.0684x over previous
#include <cuda_runtime.h>
#include <cuda_fp16.h>
#include <math_constants.h>
#include <cstdint>

#define B_  4
#define N_  4096
#define C_  256
#define NT_ 64   // key tiles of 64
#define NP_ 320  // packed projection cols: 32 f + 32 g(pre-scaled by log2e) + 256 h

// ---------------------------------------------------------------------------
// Scratch (__device__ globals; allocation-free rule)
// ---------------------------------------------------------------------------
__device__ uint4 g_xs[B_ * N_ * 64];          // x split fp16 [BN][256hi|256lo]
__device__ uint4 g_wt[NP_ * 64];              // W^T split fp16 [320][256hi|256lo]
__device__ float g_pb[NP_];                   // packed bias
__device__ uint4 g_fs[B_ * N_ * 8];           // F split fp16 [B,N,(32hi|32lo)]
__device__ uint4 g_gs[B_ * N_ * 8];           // G split fp16 [B,N,(32hi|32lo)]
__device__ uint4 g_ht[B_ * C_ * N_ / 8];      // H^T fp16 [B,C,N]

// ---------------------------------------------------------------------------
// Helpers
// ---------------------------------------------------------------------------
__device__ __forceinline__ uint32_t smem_u32(const void* p) {
    uint32_t a;
    asm("{ .reg .u64 t; cvta.to.shared.u64 t, %1; cvt.u32.u64 %0, t; }" : "=r"(a) : "l"(p));
    return a;
}
__device__ __forceinline__ void ldsm4(uint32_t* r, uint32_t addr) {
    asm volatile("ldmatrix.sync.aligned.m8n8.x4.shared.b16 {%0,%1,%2,%3}, [%4];"
        : "=r"(r[0]), "=r"(r[1]), "=r"(r[2]), "=r"(r[3]) : "r"(addr));
}
__device__ __forceinline__ void mma_f16(float* d, const uint32_t* a, uint32_t b0, uint32_t b1) {
    asm volatile("mma.sync.aligned.m16n8k16.row.col.f32.f16.f16.f32 "
        "{%0,%1,%2,%3}, {%4,%5,%6,%7}, {%8,%9}, {%0,%1,%2,%3};"
        : "+f"(d[0]), "+f"(d[1]), "+f"(d[2]), "+f"(d[3])
        : "r"(a[0]), "r"(a[1]), "r"(a[2]), "r"(a[3]), "r"(b0), "r"(b1));
}
__device__ __forceinline__ void cp16(uint32_t dst, const void* src) {
    asm volatile("cp.async.cg.shared.global [%0], [%1], 16;" :: "r"(dst), "l"(src) : "memory");
}
__device__ __forceinline__ float ex2(float x) {
    float y; asm("ex2.approx.f32 %0, %1;" : "=f"(y) : "f"(x)); return y;
}
#define CP_COMMIT()  asm volatile("cp.async.commit_group;" ::: "memory")
#define CP_WAIT(n)   asm volatile("cp.async.wait_group %0;" :: "n"(n) : "memory")

// ---------------------------------------------------------------------------
// prep_x: x fp32 [BN,256] -> xs fp16 [BN][256hi|256lo]
// ---------------------------------------------------------------------------
__global__ __launch_bounds__(256) void prep_x(const float* __restrict__ x, uint4* __restrict__ xs)
{
    int id = blockIdx.x * 256 + threadIdx.x;
    int r = id >> 5, c = id & 31;
    const float4* src = (const float4*)(x + (long)r * 256 + c * 8);
    float4 v0 = src[0], v1 = src[1];
    float vv[8] = {v0.x, v0.y, v0.z, v0.w, v1.x, v1.y, v1.z, v1.w};
    __half hv[8], lv[8];
#pragma unroll
    for (int i = 0; i < 8; i++) {
        hv[i] = __float2half_rn(vv[i]);
        lv[i] = __float2half_rn(vv[i] - __half2float(hv[i]));
    }
    xs[(long)r * 64 + c]      = *(uint4*)hv;
    xs[(long)r * 64 + 32 + c] = *(uint4*)lv;
}

// ---------------------------------------------------------------------------
// prep_w: pack [Wf|Wg*log2e|Wh]^T fp16 hi/lo + bias.
// ---------------------------------------------------------------------------
__global__ __launch_bounds__(256) void prep_w(
    const float* __restrict__ Wf, const float* __restrict__ Wg, const float* __restrict__ Wh,
    const float* __restrict__ bf, const float* __restrict__ bg, const float* __restrict__ bh,
    __half* __restrict__ wt, float* __restrict__ pb)
{
    const float L2E = 1.4426950408889634f;
    int n = blockIdx.x, k = threadIdx.x;
    float w = (n < 32) ? Wf[k * 32 + n]
            : (n < 64) ? Wg[k * 32 + (n - 32)] * L2E
                       : Wh[k * 256 + (n - 64)];
    __half hv = __float2half_rn(w);
    __half lv = __float2half_rn(w - __half2float(hv));
    wt[(long)n * 512 + k] = hv;
    wt[(long)n * 512 + 256 + k] = lv;
    if (k == 0)
        pb[n] = (n < 32) ? bf[n] : (n < 64) ? bg[n - 32] * L2E : bh[n - 64];
}

// ---------------------------------------------------------------------------
// Fused projection GEMM + transposed h epilogue (unchanged from round 9).
// ---------------------------------------------------------------------------
#define PG_STAGE 49152
#define PG_SMEM  (2 * PG_STAGE + 256)

__global__ __launch_bounds__(256) void proj_mma(
    const uint4* __restrict__ xs, const uint4* __restrict__ wt,
    const float* __restrict__ pb,
    __half* __restrict__ fsh, __half* __restrict__ gsh, __half* __restrict__ ht)
{
    extern __shared__ char smem[];
    const uint32_t sb = smem_u32(smem);
    float* sbias = (float*)(smem + 2 * PG_STAGE);
    const int tid = threadIdx.x, lane = tid & 31, wid = tid >> 5;
    const int wm = wid & 3, wn = wid >> 2;
    const int n0 = blockIdx.x * 64, m0 = blockIdx.y * 128;

    const int la_row = (((lane >> 3) & 1) << 3) | (lane & 7);
    const int la_sel = lane >> 4;
    const int lb_row = ((lane >> 4) << 3) | (lane & 7);
    const int lb_sel = (lane >> 3) & 1;

    if (tid < 64) sbias[tid] = pb[n0 + tid];

    auto issue_stage = [&](int kt, int st) {
        uint32_t base = sb + st * PG_STAGE;
#pragma unroll
        for (int i = 0; i < 4; i++) {
            int idx = tid + i * 256;
            int r = idx >> 3, c = idx & 7;
            uint32_t sw = ((c ^ (r & 7)) << 4);
            cp16(base + r * 128 + sw,          xs + (long)(m0 + r) * 64 + kt * 8 + c);
            cp16(base + 16384 + r * 128 + sw,  xs + (long)(m0 + r) * 64 + 32 + kt * 8 + c);
        }
#pragma unroll
        for (int i = 0; i < 2; i++) {
            int idx = tid + i * 256;
            int r = idx >> 3, c = idx & 7;
            uint32_t sw = ((c ^ (r & 7)) << 4);
            cp16(base + 32768 + r * 128 + sw,        wt + (long)(n0 + r) * 64 + kt * 8 + c);
            cp16(base + 32768 + 8192 + r * 128 + sw, wt + (long)(n0 + r) * 64 + 32 + kt * 8 + c);
        }
        CP_COMMIT();
    };

    issue_stage(0, 0);

    float d[2][4][4];
#pragma unroll
    for (int mh = 0; mh < 2; mh++)
#pragma unroll
        for (int i = 0; i < 4; i++)
#pragma unroll
            for (int j = 0; j < 4; j++) d[mh][i][j] = 0.f;

#pragma unroll 1
    for (int kt = 0; kt < 4; kt++) {
        if (kt < 3) { issue_stage(kt + 1, (kt + 1) & 1); CP_WAIT(1); }
        else        { CP_WAIT(0); }
        __syncthreads();
        uint32_t buf = sb + (kt & 1) * PG_STAGE;

#pragma unroll
        for (int kc = 0; kc < 4; kc++) {
            uint32_t ah[2][4], al[2][4], bh[2][4], bl[2][4];
#pragma unroll
            for (int mh = 0; mh < 2; mh++) {
                int arow = wm * 32 + mh * 16 + la_row;
                uint32_t sw = (((2 * kc + la_sel) ^ (arow & 7)) << 4);
                ldsm4(ah[mh], buf + arow * 128 + sw);
                ldsm4(al[mh], buf + 16384 + arow * 128 + sw);
            }
#pragma unroll
            for (int n16 = 0; n16 < 2; n16++) {
                int brow = wn * 32 + n16 * 16 + lb_row;
                uint32_t sw = (((2 * kc + lb_sel) ^ (brow & 7)) << 4);
                ldsm4(bh[n16], buf + 32768 + brow * 128 + sw);
                ldsm4(bl[n16], buf + 32768 + 8192 + brow * 128 + sw);
            }
#pragma unroll
            for (int mh = 0; mh < 2; mh++)
#pragma unroll
                for (int n16 = 0; n16 < 2; n16++)
#pragma unroll
                    for (int j = 0; j < 2; j++) {
                        float* dd = d[mh][n16 * 2 + j];
                        mma_f16(dd, ah[mh], bh[n16][2 * j], bh[n16][2 * j + 1]);
                        mma_f16(dd, ah[mh], bl[n16][2 * j], bl[n16][2 * j + 1]);
                        mma_f16(dd, al[mh], bh[n16][2 * j], bh[n16][2 * j + 1]);
                    }
        }
        __syncthreads();
    }

    if (blockIdx.x == 0) {
#pragma unroll
        for (int mh = 0; mh < 2; mh++) {
            const long mrow0 = m0 + wm * 32 + mh * 16 + (lane >> 2);
            const long mrow1 = mrow0 + 8;
#pragma unroll
            for (int n16 = 0; n16 < 2; n16++)
#pragma unroll
                for (int j = 0; j < 2; j++) {
                    const float* dd = d[mh][n16 * 2 + j];
                    int col = wn * 32 + n16 * 16 + j * 8 + (lane & 3) * 2;
                    float b0 = sbias[col], b1 = sbias[col + 1];
                    float v00 = dd[0] + b0, v01 = dd[1] + b1;
                    float v10 = dd[2] + b0, v11 = dd[3] + b1;
                    __half* dst = (col < 32) ? fsh : gsh;
                    int c = col & 31;
                    __half2 h0 = __floats2half2_rn(v00, v01);
                    float2 f0 = __half22float2(h0);
                    __half2 l0 = __floats2half2_rn(v00 - f0.x, v01 - f0.y);
                    *(__half2*)(dst + mrow0 * 64 + c) = h0;
                    *(__half2*)(dst + mrow0 * 64 + 32 + c) = l0;
                    __half2 h1 = __floats2half2_rn(v10, v11);
                    float2 f1 = __half22float2(h1);
                    __half2 l1 = __floats2half2_rn(v10 - f1.x, v11 - f1.y);
                    *(__half2*)(dst + mrow1 * 64 + c) = h1;
                    *(__half2*)(dst + mrow1 * 64 + 32 + c) = l1;
                }
        }
    } else {
        __half* sT = (__half*)smem;            // [64 ch][136 stride]
#pragma unroll
        for (int mh = 0; mh < 2; mh++) {
            const int r0 = wm * 32 + mh * 16 + (lane >> 2);
            const int r1 = r0 + 8;
#pragma unroll
            for (int n16 = 0; n16 < 2; n16++)
#pragma unroll
                for (int j = 0; j < 2; j++) {
                    const float* dd = d[mh][n16 * 2 + j];
                    int col = wn * 32 + n16 * 16 + j * 8 + (lane & 3) * 2;
                    float b0 = sbias[col], b1 = sbias[col + 1];
                    sT[col * 136 + r0]       = __float2half_rn(dd[0] + b0);
                    sT[(col + 1) * 136 + r0] = __float2half_rn(dd[1] + b1);
                    sT[col * 136 + r1]       = __float2half_rn(dd[2] + b0);
                    sT[(col + 1) * 136 + r1] = __float2half_rn(dd[3] + b1);
                }
        }
        __syncthreads();
        const int b = m0 >> 12;
        const int noff = m0 & (N_ - 1);
        const int ch = tid >> 2, q = tid & 3;
        uint4* dst = (uint4*)(ht + ((long)b * C_ + (n0 - 64) + ch) * N_ + noff + q * 32);
        const uint4* srcp = (const uint4*)(sT + ch * 136 + q * 32);
#pragma unroll
        for (int i = 0; i < 4; i++) dst[i] = srcp[i];
    }
}

// ---------------------------------------------------------------------------
// Attention: round-9 per-tile body, but 4-slot ring with ONE __syncthreads
// per 2 tiles (macro-iteration).  Warps drift up to ~2 tiles, so one warp's
// softmax SHFL/MUFU burst overlaps another's HMMA stream.
// Slot safety: sync at macro top guarantees tiles <= tt-1 fully read; macro tt
// stages tiles tt+2 -> slot (tt+2)&3 (held tile tt-2) and tt+3 -> (tt+3)&3
// (held tile tt-1).  Prefetch distance = 1 macro >> DRAM latency.
// ---------------------------------------------------------------------------
#define OFF_SG     0
#define STAGE_SZ   (8192 + 32768)
#define OFF_SF(s)  (16384 + (s) * STAGE_SZ)
#define OFF_SH(s)  (16384 + (s) * STAGE_SZ + 8192)
#define SMEM_TOTAL (16384 + 4 * STAGE_SZ)    // 180224 B

__global__ __launch_bounds__(256, 1) void attn_mma(
    const uint4* __restrict__ fsplit, const uint4* __restrict__ gsplit,
    const uint4* __restrict__ ht4,
    const float* __restrict__ x, const float* __restrict__ gamma, float* __restrict__ y)
{
    extern __shared__ char smem[];
    const uint32_t sb = smem_u32(smem);
    const int tid = threadIdx.x, lane = tid & 31, wid = tid >> 5;
    const int b = blockIdx.y, q0 = blockIdx.x * 128;

    const int la_row = (((lane >> 3) & 1) << 3) | (lane & 7);
    const int la_sel = lane >> 4;
    const int lb_row = ((lane >> 4) << 3) | (lane & 7);
    const int lb_sel = (lane >> 3) & 1;

    const int hr = tid >> 3, hc = tid & 7;
    const long hbase = (long)b * C_ * (N_ / 8);
    const long fbase = (long)b * N_ * 8;

    auto stage_attn = [&](int t) {
        const int sn = t & 3;
#pragma unroll
        for (int i = 0; i < 2; i++) {
            int idx = tid + i * 256;
            int r = idx >> 3, c = idx & 7;
            cp16(sb + OFF_SF(sn) + r * 128 + (((c) ^ (r & 7)) << 4),
                 fsplit + fbase + (long)(t * 64 + r) * 8 + c);
        }
#pragma unroll
        for (int i = 0; i < 8; i++) {
            int r = hr + i * 32;
            cp16(sb + OFF_SH(sn) + r * 128 + (((hc) ^ (r & 7)) << 4),
                 ht4 + hbase + (long)r * (N_ / 8) + t * 8 + hc);
        }
        CP_COMMIT();
    };

    // ---- load G tile [128 rows x 128B], swizzled ----
#pragma unroll
    for (int i = 0; i < 4; i++) {
        int idx = tid + i * 256;
        int r = idx >> 3, c = idx & 7;
        uint4 v = gsplit[(long)(b * N_ + q0 + r) * 8 + c];
        *(uint4*)(smem + OFF_SG + r * 128 + (((c) ^ (r & 7)) << 4)) = v;
    }

    // ---- prologue: stage tiles 0 and 1 ----
    stage_attn(0);
    stage_attn(1);

    // ---- hoist G A-fragments (constant over tiles) ----
    __syncthreads();
    uint32_t gh[2][4], gl[2][4];
    {
        int row = wid * 16 + la_row;
        uint32_t rowoff = sb + OFF_SG + row * 128;
#pragma unroll
        for (int kc = 0; kc < 2; kc++) {
            ldsm4(gh[kc], rowoff + ((((2 * kc) + la_sel) ^ (row & 7)) << 4));
            ldsm4(gl[kc], rowoff + ((((4 + 2 * kc) + la_sel) ^ (row & 7)) << 4));
        }
    }

    float o[32][4];
#pragma unroll
    for (int i = 0; i < 32; i++)
#pragma unroll
        for (int j = 0; j < 4; j++) o[i][j] = 0.f;
    float lsum0 = 0.f, lsum1 = 0.f;
    float mrun0 = -CUDART_INF_F, mrun1 = -CUDART_INF_F;

    // ---- one tile of work (round-9 body) ----
    auto process_tile = [&](int t) {
        const int s = t & 3;
        // MMA1: S[16x64] in log2 domain, 3-term
        float sv[8][4];
#pragma unroll
        for (int i = 0; i < 8; i++)
#pragma unroll
            for (int j = 0; j < 4; j++) sv[i][j] = 0.f;
        {
            const uint32_t sfb = sb + OFF_SF(s);
#pragma unroll
            for (int n16 = 0; n16 < 4; n16++) {
                int row = n16 * 16 + lb_row;
                uint32_t rowoff = sfb + row * 128;
                uint32_t fh0[4], fh1[4], fl0[4], fl1[4];
                ldsm4(fh0, rowoff + (((0 + lb_sel) ^ (row & 7)) << 4));
                ldsm4(fh1, rowoff + (((2 + lb_sel) ^ (row & 7)) << 4));
                ldsm4(fl0, rowoff + (((4 + lb_sel) ^ (row & 7)) << 4));
                ldsm4(fl1, rowoff + (((6 + lb_sel) ^ (row & 7)) << 4));
#pragma unroll
                for (int j = 0; j < 2; j++) {
                    float* sd = sv[n16 * 2 + j];
                    mma_f16(sd, gh[0], fh0[2 * j], fh0[2 * j + 1]);
                    mma_f16(sd, gh[1], fh1[2 * j], fh1[2 * j + 1]);
                    mma_f16(sd, gh[0], fl0[2 * j], fl0[2 * j + 1]);
                    mma_f16(sd, gh[1], fl1[2 * j], fl1[2 * j + 1]);
                    mma_f16(sd, gl[0], fh0[2 * j], fh0[2 * j + 1]);
                    mma_f16(sd, gl[1], fh1[2 * j], fh1[2 * j + 1]);
                }
            }
        }

        // softmax: row max + FA2 rescale + exp2 pack
        float mt0 = -CUDART_INF_F, mt1 = -CUDART_INF_F;
#pragma unroll
        for (int i = 0; i < 8; i++) {
            mt0 = fmaxf(mt0, fmaxf(sv[i][0], sv[i][1]));
            mt1 = fmaxf(mt1, fmaxf(sv[i][2], sv[i][3]));
        }
        mt0 = fmaxf(mt0, __shfl_xor_sync(0xFFFFFFFFu, mt0, 1));
        mt0 = fmaxf(mt0, __shfl_xor_sync(0xFFFFFFFFu, mt0, 2));
        mt1 = fmaxf(mt1, __shfl_xor_sync(0xFFFFFFFFu, mt1, 1));
        mt1 = fmaxf(mt1, __shfl_xor_sync(0xFFFFFFFFu, mt1, 2));

        const float mn0 = fmaxf(mrun0, mt0);
        const float mn1 = fmaxf(mrun1, mt1);
        const float a0 = ex2(mrun0 - mn0);   // 0 on first tile
        const float a1 = ex2(mrun1 - mn1);
        mrun0 = mn0; mrun1 = mn1;
        lsum0 *= a0; lsum1 *= a1;
        if (a0 != 1.f) {
#pragma unroll
            for (int i = 0; i < 32; i++) { o[i][0] *= a0; o[i][1] *= a0; }
        }
        if (a1 != 1.f) {
#pragma unroll
            for (int i = 0; i < 32; i++) { o[i][2] *= a1; o[i][3] *= a1; }
        }

        uint32_t phi[16];
#pragma unroll
        for (int kc = 0; kc < 4; kc++) {
#pragma unroll
            for (int half = 0; half < 2; half++) {
                float* sd = sv[2 * kc + half];
                float p0 = ex2(sd[0] - mn0);
                float p1 = ex2(sd[1] - mn0);
                float p2 = ex2(sd[2] - mn1);
                float p3 = ex2(sd[3] - mn1);
                lsum0 += p0 + p1;
                lsum1 += p2 + p3;
                __half2 h01 = __floats2half2_rn(p0, p1);
                __half2 h23 = __floats2half2_rn(p2, p3);
                phi[kc * 4 + half * 2 + 0] = *(uint32_t*)&h01;
                phi[kc * 4 + half * 2 + 1] = *(uint32_t*)&h23;
            }
        }

        // MMA2: O[16x256] += P.Ht
        {
            const uint32_t shb = sb + OFF_SH(s);
#pragma unroll
            for (int n16 = 0; n16 < 16; n16++) {
                int row = n16 * 16 + lb_row;
                uint32_t rhoff = shb + row * 128;
#pragma unroll
                for (int kc = 0; kc < 4; kc++) {
                    uint32_t bh[4];
                    ldsm4(bh, rhoff + ((((2 * kc) + lb_sel) ^ (row & 7)) << 4));
#pragma unroll
                    for (int j = 0; j < 2; j++)
                        mma_f16(o[n16 * 2 + j], &phi[kc * 4], bh[2 * j], bh[2 * j + 1]);
                }
            }
        }
    };

    // ---- macro loop: 2 tiles per barrier ----
#pragma unroll 1
    for (int tt = 0; tt < NT_; tt += 2) {
        CP_WAIT(0);          // tiles tt, tt+1 arrived (committed >= 1 macro ago)
        __syncthreads();     // all warps past tiles tt-2, tt-1 (their slots free)

        process_tile(tt);
        if (tt + 2 < NT_) stage_attn(tt + 2);   // slot (tt+2)&3 held tile tt-2
        process_tile(tt + 1);
        if (tt + 3 < NT_) stage_attn(tt + 3);   // slot (tt+3)&3 held tile tt-1
    }

    // ---- reduce l over the 4 lanes sharing a row ----
    lsum0 += __shfl_xor_sync(0xFFFFFFFFu, lsum0, 1);
    lsum0 += __shfl_xor_sync(0xFFFFFFFFu, lsum0, 2);
    lsum1 += __shfl_xor_sync(0xFFFFFFFFu, lsum1, 1);
    lsum1 += __shfl_xor_sync(0xFFFFFFFFu, lsum1, 2);
    const float inv0 = 1.f / lsum0, inv1 = 1.f / lsum1;
    const float gam = gamma[0];

    // ---- epilogue: y = gamma * O/l + x ----
    const long row0g = ((long)b * N_ + q0 + wid * 16 + (lane >> 2)) * C_;
    const long row1g = row0g + 8 * C_;
#pragma unroll
    for (int n16 = 0; n16 < 16; n16++) {
#pragma unroll
        for (int j = 0; j < 2; j++) {
            const float* od = o[n16 * 2 + j];
            int ch = n16 * 16 + j * 8 + (lane & 3) * 2;
            float2 xv = *(const float2*)(x + row0g + ch);
            float2 yv;
            yv.x = fmaf(gam, od[0] * inv0, xv.x);
            yv.y = fmaf(gam, od[1] * inv0, xv.y);
            *(float2*)(y + row0g + ch) = yv;
            xv = *(const float2*)(x + row1g + ch);
            yv.x = fmaf(gam, od[2] * inv1, xv.x);
            yv.y = fmaf(gam, od[3] * inv1, xv.y);
            *(float2*)(y + row1g + ch) = yv;
        }
    }
}

// ---------------------------------------------------------------------------
extern "C" void kernel_launch(void* const* d_in, const int* in_sizes, int n_in,
                              void* d_out, int out_size)
{
    const float* x     = (const float*)d_in[0];
    const float* Wf    = (const float*)d_in[1];
    const float* bf    = (const float*)d_in[2];
    const float* Wg    = (const float*)d_in[3];
    const float* bg    = (const float*)d_in[4];
    const float* Wh    = (const float*)d_in[5];
    const float* bh    = (const float*)d_in[6];
    const float* gamma = (const float*)d_in[7];
    float* y = (float*)d_out;

    void *xs, *wt, *pb, *fs, *gs, *ht;
    cudaGetSymbolAddress(&xs, g_xs);
    cudaGetSymbolAddress(&wt, g_wt);
    cudaGetSymbolAddress(&pb, g_pb);
    cudaGetSymbolAddress(&fs, g_fs);
    cudaGetSymbolAddress(&gs, g_gs);
    cudaGetSymbolAddress(&ht, g_ht);

    const int M = B_ * N_;

    prep_x<<<M * 32 / 256, 256>>>(x, (uint4*)xs);
    prep_w<<<NP_, 256>>>(Wf, Wg, Wh, bf, bg, bh, (__half*)wt, (float*)pb);

    cudaFuncSetAttribute(proj_mma, cudaFuncAttributeMaxDynamicSharedMemorySize, PG_SMEM);
    proj_mma<<<dim3(NP_ / 64, M / 128), 256, PG_SMEM>>>(
        (const uint4*)xs, (const uint4*)wt, (const float*)pb,
        (__half*)fs, (__half*)gs, (__half*)ht);

    cudaFuncSetAttribute(attn_mma, cudaFuncAttributeMaxDynamicSharedMemorySize, SMEM_TOTAL);
    attn_mma<<<dim3(N_ / 128, B_), 256, SMEM_TOTAL>>>(
        (const uint4*)fs, (const uint4*)gs, (const uint4*)ht, x, gamma, y);
}

// round 14
// speedup vs baseline: 1.1097x; 1.0387x over previous
#include <cuda_runtime.h>
#include <cuda_fp16.h>
#include <math_constants.h>
#include <cstdint>

#define B_  4
#define N_  4096
#define C_  256
#define NT_ 64   // key tiles of 64
#define NP_ 320  // packed projection cols: 32 f + 32 g(pre-scaled by log2e) + 256 h

// ---------------------------------------------------------------------------
// Scratch (__device__ globals; allocation-free rule)
// ---------------------------------------------------------------------------
__device__ uint4 g_wt[NP_ * 64];              // W^T split fp16 [320][256hi|256lo]
__device__ float g_pb[NP_];                   // packed bias
__device__ uint4 g_fs[B_ * N_ * 8];           // F split fp16 [B,N,(32hi|32lo)]
__device__ uint4 g_gs[B_ * N_ * 8];           // G split fp16 [B,N,(32hi|32lo)]
__device__ uint4 g_ht[B_ * C_ * N_ / 8];      // H^T fp16 [B,C,N]

// ---------------------------------------------------------------------------
// Helpers
// ---------------------------------------------------------------------------
__device__ __forceinline__ uint32_t smem_u32(const void* p) {
    uint32_t a;
    asm("{ .reg .u64 t; cvta.to.shared.u64 t, %1; cvt.u32.u64 %0, t; }" : "=r"(a) : "l"(p));
    return a;
}
__device__ __forceinline__ void ldsm4(uint32_t* r, uint32_t addr) {
    asm volatile("ldmatrix.sync.aligned.m8n8.x4.shared.b16 {%0,%1,%2,%3}, [%4];"
        : "=r"(r[0]), "=r"(r[1]), "=r"(r[2]), "=r"(r[3]) : "r"(addr));
}
__device__ __forceinline__ void mma_f16(float* d, const uint32_t* a, uint32_t b0, uint32_t b1) {
    asm volatile("mma.sync.aligned.m16n8k16.row.col.f32.f16.f16.f32 "
        "{%0,%1,%2,%3}, {%4,%5,%6,%7}, {%8,%9}, {%0,%1,%2,%3};"
        : "+f"(d[0]), "+f"(d[1]), "+f"(d[2]), "+f"(d[3])
        : "r"(a[0]), "r"(a[1]), "r"(a[2]), "r"(a[3]), "r"(b0), "r"(b1));
}
__device__ __forceinline__ void cp16(uint32_t dst, const void* src) {
    asm volatile("cp.async.cg.shared.global [%0], [%1], 16;" :: "r"(dst), "l"(src) : "memory");
}
__device__ __forceinline__ float ex2(float x) {
    float y; asm("ex2.approx.f32 %0, %1;" : "=f"(y) : "f"(x)); return y;
}
#define CP_COMMIT()  asm volatile("cp.async.commit_group;" ::: "memory")
#define CP_WAIT(n)   asm volatile("cp.async.wait_group %0;" :: "n"(n) : "memory")

// ---------------------------------------------------------------------------
// prep_w: pack [Wf|Wg*log2e|Wh]^T fp16 hi/lo + bias.
// ---------------------------------------------------------------------------
__global__ __launch_bounds__(256) void prep_w(
    const float* __restrict__ Wf, const float* __restrict__ Wg, const float* __restrict__ Wh,
    const float* __restrict__ bf, const float* __restrict__ bg, const float* __restrict__ bh,
    __half* __restrict__ wt, float* __restrict__ pb)
{
    const float L2E = 1.4426950408889634f;
    int n = blockIdx.x, k = threadIdx.x;
    float w = (n < 32) ? Wf[k * 32 + n]
            : (n < 64) ? Wg[k * 32 + (n - 32)] * L2E
                       : Wh[k * 256 + (n - 64)];
    __half hv = __float2half_rn(w);
    __half lv = __float2half_rn(w - __half2float(hv));
    wt[(long)n * 512 + k] = hv;
    wt[(long)n * 512 + 256 + k] = lv;
    if (k == 0)
        pb[n] = (n < 32) ? bf[n] : (n < 64) ? bg[n - 32] * L2E : bh[n - 64];
}

// ---------------------------------------------------------------------------
// Fused projection GEMM: reads fp32 x directly (register-pipelined LDG +
// in-kernel hi/lo split), B via cp.async.  blockIdx.x==0 -> f/g (3-term);
// blockIdx.x>=1 -> h (2-term: A-hi only; h is fp16-rounded anyway), written
// TRANSPOSED to ht[B,C,N] via smem staging.
// ---------------------------------------------------------------------------
#define PG_STAGE 49152
#define PG_SMEM  (2 * PG_STAGE + 256)

__global__ __launch_bounds__(256) void proj_mma(
    const float* __restrict__ x, const uint4* __restrict__ wt,
    const float* __restrict__ pb,
    __half* __restrict__ fsh, __half* __restrict__ gsh, __half* __restrict__ ht)
{
    extern __shared__ char smem[];
    const uint32_t sb = smem_u32(smem);
    float* sbias = (float*)(smem + 2 * PG_STAGE);
    const int tid = threadIdx.x, lane = tid & 31, wid = tid >> 5;
    const int wm = wid & 3, wn = wid >> 2;
    const int n0 = blockIdx.x * 64, m0 = blockIdx.y * 128;
    const bool fg = (blockIdx.x == 0);

    const int la_row = (((lane >> 3) & 1) << 3) | (lane & 7);
    const int la_sel = lane >> 4;
    const int lb_row = ((lane >> 4) << 3) | (lane & 7);
    const int lb_sel = (lane >> 3) & 1;

    if (tid < 64) sbias[tid] = pb[n0 + tid];

    // A register staging: 4 (row, 16B-chunk) pairs per thread, 8 float4 regs.
    float4 rbuf[8];
    auto ldg_A = [&](int kt) {
#pragma unroll
        for (int i = 0; i < 4; i++) {
            int idx = tid + i * 256;
            int r = idx >> 3, c = idx & 7;
            const float4* src = (const float4*)(x + (long)(m0 + r) * 256 + kt * 64 + c * 8);
            rbuf[2 * i]     = src[0];
            rbuf[2 * i + 1] = src[1];
        }
    };
    auto sts_A = [&](int st) {
        char* base = smem + st * PG_STAGE;
#pragma unroll
        for (int i = 0; i < 4; i++) {
            int idx = tid + i * 256;
            int r = idx >> 3, c = idx & 7;
            uint32_t sw = r * 128 + ((c ^ (r & 7)) << 4);
            float v[8] = {rbuf[2 * i].x, rbuf[2 * i].y, rbuf[2 * i].z, rbuf[2 * i].w,
                          rbuf[2 * i + 1].x, rbuf[2 * i + 1].y, rbuf[2 * i + 1].z, rbuf[2 * i + 1].w};
            __half hv[8], lv[8];
#pragma unroll
            for (int q = 0; q < 8; q++) {
                hv[q] = __float2half_rn(v[q]);
                lv[q] = __float2half_rn(v[q] - __half2float(hv[q]));
            }
            *(uint4*)(base + sw) = *(uint4*)hv;
            if (fg) *(uint4*)(base + 16384 + sw) = *(uint4*)lv;
        }
    };
    auto cp_B = [&](int kt, int st) {
        uint32_t base = sb + st * PG_STAGE + 32768;
#pragma unroll
        for (int i = 0; i < 2; i++) {
            int idx = tid + i * 256;
            int r = idx >> 3, c = idx & 7;
            uint32_t sw = r * 128 + ((c ^ (r & 7)) << 4);
            cp16(base + sw,        wt + (long)(n0 + r) * 64 + kt * 8 + c);
            cp16(base + 8192 + sw, wt + (long)(n0 + r) * 64 + 32 + kt * 8 + c);
        }
        CP_COMMIT();
    };

    // prologue
    ldg_A(0);
    sts_A(0);
    cp_B(0, 0);
    ldg_A(1);

    float d[2][4][4];
#pragma unroll
    for (int mh = 0; mh < 2; mh++)
#pragma unroll
        for (int i = 0; i < 4; i++)
#pragma unroll
            for (int j = 0; j < 4; j++) d[mh][i][j] = 0.f;

#pragma unroll 1
    for (int kt = 0; kt < 4; kt++) {
        if (kt + 1 < 4) { sts_A(kt + 1 & 1 ? (kt + 1) & 1 : (kt + 1) & 1), cp_B(kt + 1, (kt + 1) & 1); }
        if (kt + 2 < 4) ldg_A(kt + 2);
        if (kt + 1 < 4) { CP_WAIT(1); } else { CP_WAIT(0); }
        __syncthreads();
        char* bufc = smem + (kt & 1) * PG_STAGE;
        uint32_t buf = sb + (kt & 1) * PG_STAGE;
        (void)bufc;

#pragma unroll
        for (int kc = 0; kc < 4; kc++) {
            uint32_t ah[2][4], al[2][4], bh[2][4], bl[2][4];
#pragma unroll
            for (int mh = 0; mh < 2; mh++) {
                int arow = wm * 32 + mh * 16 + la_row;
                uint32_t sw = (((2 * kc + la_sel) ^ (arow & 7)) << 4);
                ldsm4(ah[mh], buf + arow * 128 + sw);
                if (fg) ldsm4(al[mh], buf + 16384 + arow * 128 + sw);
            }
#pragma unroll
            for (int n16 = 0; n16 < 2; n16++) {
                int brow = wn * 32 + n16 * 16 + lb_row;
                uint32_t sw = (((2 * kc + lb_sel) ^ (brow & 7)) << 4);
                ldsm4(bh[n16], buf + 32768 + brow * 128 + sw);
                ldsm4(bl[n16], buf + 32768 + 8192 + brow * 128 + sw);
            }
#pragma unroll
            for (int mh = 0; mh < 2; mh++)
#pragma unroll
                for (int n16 = 0; n16 < 2; n16++)
#pragma unroll
                    for (int j = 0; j < 2; j++) {
                        float* dd = d[mh][n16 * 2 + j];
                        mma_f16(dd, ah[mh], bh[n16][2 * j], bh[n16][2 * j + 1]);
                        mma_f16(dd, ah[mh], bl[n16][2 * j], bl[n16][2 * j + 1]);
                        if (fg) mma_f16(dd, al[mh], bh[n16][2 * j], bh[n16][2 * j + 1]);
                    }
        }
        __syncthreads();
    }

    if (fg) {
        // ---- f/g epilogue: hi/lo split layout ----
#pragma unroll
        for (int mh = 0; mh < 2; mh++) {
            const long mrow0 = m0 + wm * 32 + mh * 16 + (lane >> 2);
            const long mrow1 = mrow0 + 8;
#pragma unroll
            for (int n16 = 0; n16 < 2; n16++)
#pragma unroll
                for (int j = 0; j < 2; j++) {
                    const float* dd = d[mh][n16 * 2 + j];
                    int col = wn * 32 + n16 * 16 + j * 8 + (lane & 3) * 2;
                    float b0 = sbias[col], b1 = sbias[col + 1];
                    float v00 = dd[0] + b0, v01 = dd[1] + b1;
                    float v10 = dd[2] + b0, v11 = dd[3] + b1;
                    __half* dst = (col < 32) ? fsh : gsh;
                    int c = col & 31;
                    __half2 h0 = __floats2half2_rn(v00, v01);
                    float2 f0 = __half22float2(h0);
                    __half2 l0 = __floats2half2_rn(v00 - f0.x, v01 - f0.y);
                    *(__half2*)(dst + mrow0 * 64 + c) = h0;
                    *(__half2*)(dst + mrow0 * 64 + 32 + c) = l0;
                    __half2 h1 = __floats2half2_rn(v10, v11);
                    float2 f1 = __half22float2(h1);
                    __half2 l1 = __floats2half2_rn(v10 - f1.x, v11 - f1.y);
                    *(__half2*)(dst + mrow1 * 64 + c) = h1;
                    *(__half2*)(dst + mrow1 * 64 + 32 + c) = l1;
                }
        }
    } else {
        // ---- h epilogue: transpose via smem, write ht[B,C,N] coalesced ----
        __half* sT = (__half*)smem;            // [64 ch][136 stride]
#pragma unroll
        for (int mh = 0; mh < 2; mh++) {
            const int r0 = wm * 32 + mh * 16 + (lane >> 2);
            const int r1 = r0 + 8;
#pragma unroll
            for (int n16 = 0; n16 < 2; n16++)
#pragma unroll
                for (int j = 0; j < 2; j++) {
                    const float* dd = d[mh][n16 * 2 + j];
                    int col = wn * 32 + n16 * 16 + j * 8 + (lane & 3) * 2;
                    float b0 = sbias[col], b1 = sbias[col + 1];
                    sT[col * 136 + r0]       = __float2half_rn(dd[0] + b0);
                    sT[(col + 1) * 136 + r0] = __float2half_rn(dd[1] + b1);
                    sT[col * 136 + r1]       = __float2half_rn(dd[2] + b0);
                    sT[(col + 1) * 136 + r1] = __float2half_rn(dd[3] + b1);
                }
        }
        __syncthreads();
        const int b = m0 >> 12;
        const int noff = m0 & (N_ - 1);
        const int ch = tid >> 2, q = tid & 3;
        uint4* dst = (uint4*)(ht + ((long)b * C_ + (n0 - 64) + ch) * N_ + noff + q * 32);
        const uint4* srcp = (const uint4*)(sT + ch * 136 + q * 32);
#pragma unroll
        for (int i = 0; i < 4; i++) dst[i] = srcp[i];
    }
}

// ---------------------------------------------------------------------------
// Attention: round-9 kernel VERBATIM (best known: 140.2 us).
// block = 128 q-rows x batch, 8 warps, one m16 row-slice each.
// MMA1 3-term fp16 / MMA2 1-term; FA2 running-max; log2-domain softmax (ex2);
// 3-stage cp.async ring; one __syncthreads per tile.
// ---------------------------------------------------------------------------
#define OFF_SG     0
#define STAGE_SZ   (8192 + 32768)
#define OFF_SF(s)  (16384 + (s) * STAGE_SZ)
#define OFF_SH(s)  (16384 + (s) * STAGE_SZ + 8192)
#define SMEM_TOTAL (16384 + 3 * STAGE_SZ)    // 136 KB

__global__ __launch_bounds__(256, 1) void attn_mma(
    const uint4* __restrict__ fsplit, const uint4* __restrict__ gsplit,
    const uint4* __restrict__ ht4,
    const float* __restrict__ x, const float* __restrict__ gamma, float* __restrict__ y)
{
    extern __shared__ char smem[];
    const uint32_t sb = smem_u32(smem);
    const int tid = threadIdx.x, lane = tid & 31, wid = tid >> 5;
    const int b = blockIdx.y, q0 = blockIdx.x * 128;

    const int la_row = (((lane >> 3) & 1) << 3) | (lane & 7);
    const int la_sel = lane >> 4;
    const int lb_row = ((lane >> 4) << 3) | (lane & 7);
    const int lb_sel = (lane >> 3) & 1;

    const int hr = tid >> 3, hc = tid & 7;
    const long hbase = (long)b * C_ * (N_ / 8);
    const long fbase = (long)b * N_ * 8;

    auto stage_attn = [&](int t) {
        const int sn = t % 3;
#pragma unroll
        for (int i = 0; i < 2; i++) {
            int idx = tid + i * 256;
            int r = idx >> 3, c = idx & 7;
            cp16(sb + OFF_SF(sn) + r * 128 + (((c) ^ (r & 7)) << 4),
                 fsplit + fbase + (long)(t * 64 + r) * 8 + c);
        }
#pragma unroll
        for (int i = 0; i < 8; i++) {
            int r = hr + i * 32;
            cp16(sb + OFF_SH(sn) + r * 128 + (((hc) ^ (r & 7)) << 4),
                 ht4 + hbase + (long)r * (N_ / 8) + t * 8 + hc);
        }
        CP_COMMIT();
    };

    // ---- load G tile [128 rows x 128B], swizzled ----
#pragma unroll
    for (int i = 0; i < 4; i++) {
        int idx = tid + i * 256;
        int r = idx >> 3, c = idx & 7;
        uint4 v = gsplit[(long)(b * N_ + q0 + r) * 8 + c];
        *(uint4*)(smem + OFF_SG + r * 128 + (((c) ^ (r & 7)) << 4)) = v;
    }

    // ---- prologue: issue stages 0 and 1 ----
    stage_attn(0);
    stage_attn(1);

    // ---- hoist G A-fragments (constant over tiles) ----
    __syncthreads();
    uint32_t gh[2][4], gl[2][4];
    {
        int row = wid * 16 + la_row;
        uint32_t rowoff = sb + OFF_SG + row * 128;
#pragma unroll
        for (int kc = 0; kc < 2; kc++) {
            ldsm4(gh[kc], rowoff + ((((2 * kc) + la_sel) ^ (row & 7)) << 4));
            ldsm4(gl[kc], rowoff + ((((4 + 2 * kc) + la_sel) ^ (row & 7)) << 4));
        }
    }

    float o[32][4];
#pragma unroll
    for (int i = 0; i < 32; i++)
#pragma unroll
        for (int j = 0; j < 4; j++) o[i][j] = 0.f;
    float lsum0 = 0.f, lsum1 = 0.f;
    float mrun0 = -CUDART_INF_F, mrun1 = -CUDART_INF_F;

#pragma unroll 1
    for (int t = 0; t < NT_; t++) {
        const int s = t % 3;
        CP_WAIT(1);
        __syncthreads();

        // ---- MMA1(t): S[16x64] in log2 domain, 3-term ----
        float sv[8][4];
#pragma unroll
        for (int i = 0; i < 8; i++)
#pragma unroll
            for (int j = 0; j < 4; j++) sv[i][j] = 0.f;

        {
            const uint32_t sfb = sb + OFF_SF(s);
#pragma unroll
            for (int n16 = 0; n16 < 4; n16++) {
                int row = n16 * 16 + lb_row;
                uint32_t rowoff = sfb + row * 128;
                uint32_t fh0[4], fh1[4], fl0[4], fl1[4];
                ldsm4(fh0, rowoff + (((0 + lb_sel) ^ (row & 7)) << 4));
                ldsm4(fh1, rowoff + (((2 + lb_sel) ^ (row & 7)) << 4));
                ldsm4(fl0, rowoff + (((4 + lb_sel) ^ (row & 7)) << 4));
                ldsm4(fl1, rowoff + (((6 + lb_sel) ^ (row & 7)) << 4));
#pragma unroll
                for (int j = 0; j < 2; j++) {
                    float* sd = sv[n16 * 2 + j];
                    mma_f16(sd, gh[0], fh0[2 * j], fh0[2 * j + 1]);
                    mma_f16(sd, gh[1], fh1[2 * j], fh1[2 * j + 1]);
                    mma_f16(sd, gh[0], fl0[2 * j], fl0[2 * j + 1]);
                    mma_f16(sd, gh[1], fl1[2 * j], fl1[2 * j + 1]);
                    mma_f16(sd, gl[0], fh0[2 * j], fh0[2 * j + 1]);
                    mma_f16(sd, gl[1], fh1[2 * j], fh1[2 * j + 1]);
                }
            }
        }

        // ---- softmax(t): per-tile row max + FA2 rescale + exp2 pack ----
        float mt0 = -CUDART_INF_F, mt1 = -CUDART_INF_F;
#pragma unroll
        for (int i = 0; i < 8; i++) {
            mt0 = fmaxf(mt0, fmaxf(sv[i][0], sv[i][1]));
            mt1 = fmaxf(mt1, fmaxf(sv[i][2], sv[i][3]));
        }
        mt0 = fmaxf(mt0, __shfl_xor_sync(0xFFFFFFFFu, mt0, 1));
        mt0 = fmaxf(mt0, __shfl_xor_sync(0xFFFFFFFFu, mt0, 2));
        mt1 = fmaxf(mt1, __shfl_xor_sync(0xFFFFFFFFu, mt1, 1));
        mt1 = fmaxf(mt1, __shfl_xor_sync(0xFFFFFFFFu, mt1, 2));

        const float mn0 = fmaxf(mrun0, mt0);
        const float mn1 = fmaxf(mrun1, mt1);
        const float a0 = ex2(mrun0 - mn0);   // 0 on first tile
        const float a1 = ex2(mrun1 - mn1);
        mrun0 = mn0; mrun1 = mn1;
        lsum0 *= a0; lsum1 *= a1;
        if (a0 != 1.f) {
#pragma unroll
            for (int i = 0; i < 32; i++) { o[i][0] *= a0; o[i][1] *= a0; }
        }
        if (a1 != 1.f) {
#pragma unroll
            for (int i = 0; i < 32; i++) { o[i][2] *= a1; o[i][3] *= a1; }
        }

        uint32_t phi[16];
#pragma unroll
        for (int kc = 0; kc < 4; kc++) {
#pragma unroll
            for (int half = 0; half < 2; half++) {
                float* sd = sv[2 * kc + half];
                float p0 = ex2(sd[0] - mn0);
                float p1 = ex2(sd[1] - mn0);
                float p2 = ex2(sd[2] - mn1);
                float p3 = ex2(sd[3] - mn1);
                lsum0 += p0 + p1;
                lsum1 += p2 + p3;
                __half2 h01 = __floats2half2_rn(p0, p1);
                __half2 h23 = __floats2half2_rn(p2, p3);
                phi[kc * 4 + half * 2 + 0] = *(uint32_t*)&h01;
                phi[kc * 4 + half * 2 + 1] = *(uint32_t*)&h23;
            }
        }

        // ---- MMA2(t): O[16x256] += P.Ht ----
        {
            const uint32_t shb = sb + OFF_SH(s);
#pragma unroll
            for (int n16 = 0; n16 < 16; n16++) {
                int row = n16 * 16 + lb_row;
                uint32_t rhoff = shb + row * 128;
#pragma unroll
                for (int kc = 0; kc < 4; kc++) {
                    uint32_t bh[4];
                    ldsm4(bh, rhoff + ((((2 * kc) + lb_sel) ^ (row & 7)) << 4));
#pragma unroll
                    for (int j = 0; j < 2; j++)
                        mma_f16(o[n16 * 2 + j], &phi[kc * 4], bh[2 * j], bh[2 * j + 1]);
                }
            }
        }

        // ---- issue stage t+2 (slot (t+2)%3 last read at iter t-1) ----
        if (t + 2 < NT_) stage_attn(t + 2);
        else CP_COMMIT();
    }

    // ---- reduce l over the 4 lanes sharing a row ----
    lsum0 += __shfl_xor_sync(0xFFFFFFFFu, lsum0, 1);
    lsum0 += __shfl_xor_sync(0xFFFFFFFFu, lsum0, 2);
    lsum1 += __shfl_xor_sync(0xFFFFFFFFu, lsum1, 1);
    lsum1 += __shfl_xor_sync(0xFFFFFFFFu, lsum1, 2);
    const float inv0 = 1.f / lsum0, inv1 = 1.f / lsum1;
    const float gam = gamma[0];

    // ---- epilogue: y = gamma * O/l + x ----
    const long row0g = ((long)b * N_ + q0 + wid * 16 + (lane >> 2)) * C_;
    const long row1g = row0g + 8 * C_;
#pragma unroll
    for (int n16 = 0; n16 < 16; n16++) {
#pragma unroll
        for (int j = 0; j < 2; j++) {
            const float* od = o[n16 * 2 + j];
            int ch = n16 * 16 + j * 8 + (lane & 3) * 2;
            float2 xv = *(const float2*)(x + row0g + ch);
            float2 yv;
            yv.x = fmaf(gam, od[0] * inv0, xv.x);
            yv.y = fmaf(gam, od[1] * inv0, xv.y);
            *(float2*)(y + row0g + ch) = yv;
            xv = *(const float2*)(x + row1g + ch);
            yv.x = fmaf(gam, od[2] * inv1, xv.x);
            yv.y = fmaf(gam, od[3] * inv1, xv.y);
            *(float2*)(y + row1g + ch) = yv;
        }
    }
}

// ---------------------------------------------------------------------------
extern "C" void kernel_launch(void* const* d_in, const int* in_sizes, int n_in,
                              void* d_out, int out_size)
{
    const float* x     = (const float*)d_in[0];
    const float* Wf    = (const float*)d_in[1];
    const float* bf    = (const float*)d_in[2];
    const float* Wg    = (const float*)d_in[3];
    const float* bg    = (const float*)d_in[4];
    const float* Wh    = (const float*)d_in[5];
    const float* bh    = (const float*)d_in[6];
    const float* gamma = (const float*)d_in[7];
    float* y = (float*)d_out;

    void *wt, *pb, *fs, *gs, *ht;
    cudaGetSymbolAddress(&wt, g_wt);
    cudaGetSymbolAddress(&pb, g_pb);
    cudaGetSymbolAddress(&fs, g_fs);
    cudaGetSymbolAddress(&gs, g_gs);
    cudaGetSymbolAddress(&ht, g_ht);

    const int M = B_ * N_;

    prep_w<<<NP_, 256>>>(Wf, Wg, Wh, bf, bg, bh, (__half*)wt, (float*)pb);

    cudaFuncSetAttribute(proj_mma, cudaFuncAttributeMaxDynamicSharedMemorySize, PG_SMEM);
    proj_mma<<<dim3(NP_ / 64, M / 128), 256, PG_SMEM>>>(
        x, (const uint4*)wt, (const float*)pb,
        (__half*)fs, (__half*)gs, (__half*)ht);

    cudaFuncSetAttribute(attn_mma, cudaFuncAttributeMaxDynamicSharedMemorySize, SMEM_TOTAL);
    attn_mma<<<dim3(N_ / 128, B_), 256, SMEM_TOTAL>>>(
        (const uint4*)fs, (const uint4*)gs, (const uint4*)ht, x, gamma, y);
}